// round 7
// baseline (speedup 1.0000x reference)
#include <cuda_runtime.h>
#include <cuda_fp16.h>
#include <cstdint>

// ---------------------------------------------------------------------------
// BasisConvLayer (mode='conv', linear hat basis 4x4, F_in=F_out=16)
//
// FP16 table with REDUNDANT-U layout so a bilinear 2x2 cell is one contiguous
// 128B span:  T2[node][up:3][v:4][us:2][fout:16]  (u = up+us; middle u rows
// stored twice; 768 B/node, 76.8 MB -> L2-resident).
//
//   Kernel 1 (build): warp <-> (node, u-half); W column in f32x2 regs;
//     x via prefetched LDG + shfl; fma.rn.f32x2; 1-2 coalesced 8B stores.
//   Kernel 2 (edge): 4 lanes/edge x 2 edges/thread; 2 adjacent LDG.128/lane
//     (same/adjacent 128B line); 4 shfl combine; one red.global.add.v4/lane.
// ---------------------------------------------------------------------------

#define MAX_NODES 100000
#define F 16
#define NB 4
#define TROWH 384                 // halves per node: 3*4*2*16

__device__ __align__(16) __half g_table[(size_t)MAX_NODES * TROWH];

#define PACK_F32X2(out, lo, hi) \
    asm("mov.b64 %0, {%1, %2};" : "=l"(out) : "f"(lo), "f"(hi))
#define UNPACK_F32X2(lo, hi, in) \
    asm("mov.b64 {%0, %1}, %2;" : "=f"(lo), "=f"(hi) : "l"(in))
#define FMA_F32X2(d, a, b, c) \
    asm("fma.rn.f32x2 %0, %1, %2, %3;" : "=l"(d) : "l"(a), "l"(b), "l"(c))
// memory halves order [lo, hi]
#define CVT_F16X2(u, lo, hi) \
    asm("cvt.rn.f16x2.f32 %0, %1, %2;" : "=r"(u) : "f"(hi), "f"(lo))

// ---------------------------------------------------------------------------
// Kernel 1: build. Warp covers u-half {2p, 2p+1} x v(4) x q(4) of one node.
// ---------------------------------------------------------------------------
__global__ __launch_bounds__(256) void build_table_kernel(
    const float* __restrict__ x,
    const float* __restrict__ w,
    int n_nodes)
{
    int lane  = threadIdx.x & 31;
    int warpG = blockIdx.x * 8 + (threadIdx.x >> 5);
    int p     = warpG & 1;
    int u     = (lane >> 4) + 2 * p;     // 0..3
    int v     = (lane >> 2) & 3;
    int q     = lane & 3;
    int k     = u * 4 + v;               // cell index into W

    const float4* wf4 = reinterpret_cast<const float4*>(w);
    unsigned long long wlo[F], whi[F];
#pragma unroll
    for (int fin = 0; fin < F; fin++) {
        float4 wv = wf4[k * 64 + fin * 4 + q];
        PACK_F32X2(wlo[fin], wv.x, wv.y);
        PACK_F32X2(whi[fin], wv.z, wv.w);
    }

    uint2* tb = reinterpret_cast<uint2*>(g_table);
    int node        = warpG >> 1;
    int node_stride = (gridDim.x * 8) >> 1;

    // prefetch x for first node
    float xl_next = 0.f;
    if (node < n_nodes && lane < F)
        xl_next = x[(size_t)node * F + lane];

    for (; node < n_nodes; node += node_stride) {
        float xl = xl_next;
        int nn = node + node_stride;
        if (nn < n_nodes && lane < F)
            xl_next = x[(size_t)nn * F + lane];

        unsigned long long a0 = 0, a1 = 0;
#pragma unroll
        for (int fin = 0; fin < F; fin++) {
            float xv = __shfl_sync(0xffffffffu, xl, fin);
            unsigned long long xx;
            PACK_F32X2(xx, xv, xv);
            FMA_F32X2(a0, xx, wlo[fin], a0);
            FMA_F32X2(a1, xx, whi[fin], a1);
        }
        float f0, f1, f2, f3;
        UNPACK_F32X2(f0, f1, a0);
        UNPACK_F32X2(f2, f3, a1);
        uint2 val;
        CVT_F16X2(val.x, f0, f1);
        CVT_F16X2(val.y, f2, f3);

        size_t base = (size_t)node * 96;     // uint2 per node
        if (u <= 2) tb[base + u * 32 + v * 8 + q] = val;            // us=0
        if (u >= 1) tb[base + (u - 1) * 32 + v * 8 + 4 + q] = val;  // us=1
    }
}

// ---------------------------------------------------------------------------
// Kernel 2: 4 lanes/edge, 2 edges/thread.
//   lane sl: us = sl>>1 (u offset), h = sl&1 (fout half)
//   loads uint4 at node*48 + iu*16 + iv*4 + sl  (v=iv, us, h)
//     and                          ... + sl + 4 (v=iv+1, us, h)
// ---------------------------------------------------------------------------
#define EPB 128
__global__ __launch_bounds__(256) void edge_kernel(
    const int* __restrict__ ei,
    const float* __restrict__ attr,
    float* __restrict__ out,
    int n_edges)
{
    int tid = threadIdx.x;
    int sl  = tid & 3;
    int g   = tid >> 2;
    int us  = sl >> 1;
    int h   = sl & 1;

    const uint4* tb = reinterpret_cast<const uint4*>(g_table);

    int  e[2] = { blockIdx.x * EPB + g, blockIdx.x * EPB + g + 64 };
    bool val[2];
    int  row[2];
    uint4 u0[2], u1[2];
    float wA[2], wB[2];

#pragma unroll
    for (int i = 0; i < 2; i++) {
        val[i] = (e[i] < n_edges);
        int ec = val[i] ? e[i] : (n_edges - 1);

        row[i]   = ei[ec];
        int col  = ei[n_edges + ec];
        float2 a = reinterpret_cast<const float2*>(attr)[ec];

        float sx = fmaf(a.x, 1.5f, 1.5f);
        float sy = fmaf(a.y, 1.5f, 1.5f);
        float ixf = fminf(fmaxf(floorf(sx), 0.f), 2.f);
        float iyf = fminf(fmaxf(floorf(sy), 0.f), 2.f);
        float fx = sx - ixf;
        float fy = sy - iyf;
        int iu = (int)ixf;
        int iv = (int)iyf;

        float w11 = fx * fy;
        float w10 = fx - w11;
        float w01 = fy - w11;
        float w00 = 1.f - fx - fy + w11;

        wA[i] = us ? w10 : w00;   // v = iv   row, u = iu+us
        wB[i] = us ? w11 : w01;   // v = iv+1 row

        size_t bi = (size_t)col * 48 + iu * 16 + iv * 4 + sl;
        u0[i] = tb[bi];
        u1[i] = tb[bi + 4];
    }

#pragma unroll
    for (int i = 0; i < 2; i++) {
        const __half2* h0 = reinterpret_cast<const __half2*>(&u0[i]);
        const __half2* h1 = reinterpret_cast<const __half2*>(&u1[i]);
        float p[8];
#pragma unroll
        for (int j = 0; j < 4; j++) {
            float2 f0 = __half22float2(h0[j]);
            float2 f1 = __half22float2(h1[j]);
            p[2 * j]     = fmaf(wA[i], f0.x, wB[i] * f1.x);
            p[2 * j + 1] = fmaf(wA[i], f0.y, wB[i] * f1.y);
        }
        // exchange with partner lane (other us, same h): send the half the
        // partner finalizes, keep mine.
        float fin0, fin1, fin2, fin3;
        {
            float s0 = us ? p[0] : p[4];
            float s1 = us ? p[1] : p[5];
            float s2 = us ? p[2] : p[6];
            float s3 = us ? p[3] : p[7];
            float r0 = __shfl_xor_sync(0xffffffffu, s0, 2);
            float r1 = __shfl_xor_sync(0xffffffffu, s1, 2);
            float r2 = __shfl_xor_sync(0xffffffffu, s2, 2);
            float r3 = __shfl_xor_sync(0xffffffffu, s3, 2);
            fin0 = (us ? p[4] : p[0]) + r0;
            fin1 = (us ? p[5] : p[1]) + r1;
            fin2 = (us ? p[6] : p[2]) + r2;
            fin3 = (us ? p[7] : p[3]) + r3;
        }
        if (val[i]) {
            float* op = out + (size_t)row[i] * F + h * 8 + us * 4;
            asm volatile("red.global.add.v4.f32 [%0], {%1, %2, %3, %4};"
                         :: "l"(op), "f"(fin0), "f"(fin1), "f"(fin2), "f"(fin3)
                         : "memory");
        }
    }
}

// ---------------------------------------------------------------------------
extern "C" void kernel_launch(void* const* d_in, const int* in_sizes, int n_in,
                              void* d_out, int out_size)
{
    const float* x    = (const float*)d_in[0];
    const int*   ei   = (const int*)d_in[1];
    const float* attr = (const float*)d_in[2];
    const float* w    = (const float*)d_in[3];
    float*       out  = (float*)d_out;

    int n_nodes = in_sizes[0] / F;       // 100000
    int n_edges = in_sizes[1] / 2;       // 1600000

    cudaMemsetAsync(d_out, 0, (size_t)out_size * sizeof(float));

    build_table_kernel<<<1184, 256>>>(x, w, n_nodes);

    int ek_blocks = (n_edges + EPB - 1) / EPB;
    edge_kernel<<<ek_blocks, 256>>>(ei, attr, out, n_edges);
}

// round 8
// speedup vs baseline: 1.3590x; 1.3590x over previous
#include <cuda_runtime.h>
#include <cuda_fp16.h>
#include <cstdint>

// ---------------------------------------------------------------------------
// BasisConvLayer (mode='conv', linear hat basis 4x4, F_in=F_out=16)
//
// FP16 table  T[node][u:4][v:4][fout:16]  (512 B/node, 51 MB -> L2-friendly).
//   Kernel 1 (build): warp <-> (node-batch of 8, k-half); W column in f32x2
//     regs; one coalesced 512B x-load per 8 nodes + prefetch; shfl distribute;
//     fma.rn.f32x2; 256B/warp coalesced stores.
//   Kernel 2 (edge): 4 lanes/edge x 4 edges/thread (high MLP); 2 LDG.128/lane;
//     lane-pair shfl combine; one red.global.add.v4.f32 per lane per edge.
// ---------------------------------------------------------------------------

#define MAX_NODES 100000
#define F 16
#define NB 4
#define TROWH 256                 // halves per node

__device__ __align__(16) __half g_table[(size_t)MAX_NODES * TROWH];

#define PACK_F32X2(out, lo, hi) \
    asm("mov.b64 %0, {%1, %2};" : "=l"(out) : "f"(lo), "f"(hi))
#define UNPACK_F32X2(lo, hi, in) \
    asm("mov.b64 {%0, %1}, %2;" : "=f"(lo), "=f"(hi) : "l"(in))
#define FMA_F32X2(d, a, b, c) \
    asm("fma.rn.f32x2 %0, %1, %2, %3;" : "=l"(d) : "l"(a), "l"(b), "l"(c))
// memory halves order [lo, hi]
#define CVT_F16X2(u, lo, hi) \
    asm("cvt.rn.f16x2.f32 %0, %1, %2;" : "=r"(u) : "f"(hi), "f"(lo))

// ---------------------------------------------------------------------------
// Kernel 1: build table. Warp processes 8 nodes/iter for its k-half.
// ---------------------------------------------------------------------------
__global__ __launch_bounds__(256) void build_table_kernel(
    const float* __restrict__ x,
    const float* __restrict__ w,
    int n_nodes)
{
    int lane  = threadIdx.x & 31;
    int warpG = blockIdx.x * 8 + (threadIdx.x >> 5);
    int p     = warpG & 1;                 // k-half
    int k     = (lane >> 2) + 8 * p;       // cell 0..15
    int q     = lane & 3;                  // fout quad

    const float4* wf4 = reinterpret_cast<const float4*>(w);
    unsigned long long wlo[F], whi[F];
#pragma unroll
    for (int fin = 0; fin < F; fin++) {
        float4 wv = wf4[k * 64 + fin * 4 + q];
        PACK_F32X2(wlo[fin], wv.x, wv.y);
        PACK_F32X2(whi[fin], wv.z, wv.w);
    }

    const float4* xf4 = reinterpret_cast<const float4*>(x);
    uint2* tb = reinterpret_cast<uint2*>(g_table);

    int group        = warpG >> 1;               // 8-node group index
    int group_stride = (gridDim.x * 8) >> 1;
    int n_groups     = (n_nodes + 7) >> 3;

    // lane l fetches float4 #l of the 8-node x batch (128 floats)
    int my_node_off = lane >> 2;     // 0..7
    int my_part     = lane & 3;      // float4 within node

    // prefetch first batch
    float4 xb_next = make_float4(0.f, 0.f, 0.f, 0.f);
    {
        int n = group * 8 + my_node_off;
        if (group < n_groups && n < n_nodes)
            xb_next = xf4[(size_t)n * 4 + my_part];
    }

    for (int grp = group; grp < n_groups; grp += group_stride) {
        float4 xb = xb_next;
        {
            int ng = grp + group_stride;
            int n  = ng * 8 + my_node_off;
            if (ng < n_groups && n < n_nodes)
                xb_next = xf4[(size_t)n * 4 + my_part];
        }

#pragma unroll
        for (int nl = 0; nl < 8; nl++) {
            int node = grp * 8 + nl;
            unsigned long long a0 = 0, a1 = 0;
#pragma unroll
            for (int j = 0; j < 4; j++) {
                int src = nl * 4 + j;
                float v0 = __shfl_sync(0xffffffffu, xb.x, src);
                float v1 = __shfl_sync(0xffffffffu, xb.y, src);
                float v2 = __shfl_sync(0xffffffffu, xb.z, src);
                float v3 = __shfl_sync(0xffffffffu, xb.w, src);
                unsigned long long xx;
                PACK_F32X2(xx, v0, v0);
                FMA_F32X2(a0, xx, wlo[j * 4 + 0], a0);
                FMA_F32X2(a1, xx, whi[j * 4 + 0], a1);
                PACK_F32X2(xx, v1, v1);
                FMA_F32X2(a0, xx, wlo[j * 4 + 1], a0);
                FMA_F32X2(a1, xx, whi[j * 4 + 1], a1);
                PACK_F32X2(xx, v2, v2);
                FMA_F32X2(a0, xx, wlo[j * 4 + 2], a0);
                FMA_F32X2(a1, xx, whi[j * 4 + 2], a1);
                PACK_F32X2(xx, v3, v3);
                FMA_F32X2(a0, xx, wlo[j * 4 + 3], a0);
                FMA_F32X2(a1, xx, whi[j * 4 + 3], a1);
            }
            if (node < n_nodes) {
                float f0, f1, f2, f3;
                UNPACK_F32X2(f0, f1, a0);
                UNPACK_F32X2(f2, f3, a1);
                uint2 val;
                CVT_F16X2(val.x, f0, f1);
                CVT_F16X2(val.y, f2, f3);
                tb[(size_t)node * 64 + k * 4 + q] = val;  // 256B/warp
            }
        }
    }
}

// ---------------------------------------------------------------------------
// Kernel 2: 4 lanes/edge, 4 edges/thread.
// ---------------------------------------------------------------------------
#define UNR 4
#define EPB 256   // 256 threads / 4 lanes * 4 edges
__global__ __launch_bounds__(256) void edge_kernel(
    const int* __restrict__ ei,
    const float* __restrict__ attr,
    float* __restrict__ out,
    int n_edges)
{
    int tid = threadIdx.x;
    int sl  = tid & 3;
    int g   = tid >> 2;

    const uint4* tb = reinterpret_cast<const uint4*>(g_table);

    bool val[UNR];
    int  row[UNR];
    uint4 u0[UNR], u1[UNR];
    float wa[UNR], wb[UNR];

#pragma unroll
    for (int i = 0; i < UNR; i++) {
        int e = blockIdx.x * EPB + g + 64 * i;
        val[i] = (e < n_edges);
        int ec = val[i] ? e : (n_edges - 1);

        row[i]   = ei[ec];
        int col  = ei[n_edges + ec];
        float2 a = reinterpret_cast<const float2*>(attr)[ec];

        float sx = fmaf(a.x, 1.5f, 1.5f);
        float sy = fmaf(a.y, 1.5f, 1.5f);
        float ixf = fminf(fmaxf(floorf(sx), 0.f), 2.f);
        float iyf = fminf(fmaxf(floorf(sy), 0.f), 2.f);
        float fx = sx - ixf;
        float fy = sy - iyf;
        int iu = (int)ixf;
        int iv = (int)iyf;

        float w11 = fx * fy;
        float w10 = fx - w11;
        float w01 = fy - w11;
        float w00 = 1.f - fx - fy + w11;

        wa[i] = (sl < 2) ? w00 : w01;   // u=iu   (v per lane)
        wb[i] = (sl < 2) ? w10 : w11;   // u=iu+1

        size_t bi = (size_t)col * 32 + (iu * 4 + iv) * 2 + sl;
        u0[i] = tb[bi];
        u1[i] = tb[bi + 8];
    }

#pragma unroll
    for (int i = 0; i < UNR; i++) {
        const __half2* h0 = reinterpret_cast<const __half2*>(&u0[i]);
        const __half2* h1 = reinterpret_cast<const __half2*>(&u1[i]);
        float p[8];
#pragma unroll
        for (int j = 0; j < 4; j++) {
            float2 f0 = __half22float2(h0[j]);
            float2 f1 = __half22float2(h1[j]);
            p[2 * j]     = fmaf(wa[i], f0.x, wb[i] * f1.x);
            p[2 * j + 1] = fmaf(wa[i], f0.y, wb[i] * f1.y);
        }
        bool hi = (sl & 2);
        float fin0, fin1, fin2, fin3;
        {
            float s0 = hi ? p[0] : p[4];
            float s1 = hi ? p[1] : p[5];
            float s2 = hi ? p[2] : p[6];
            float s3 = hi ? p[3] : p[7];
            float r0 = __shfl_xor_sync(0xffffffffu, s0, 2);
            float r1 = __shfl_xor_sync(0xffffffffu, s1, 2);
            float r2 = __shfl_xor_sync(0xffffffffu, s2, 2);
            float r3 = __shfl_xor_sync(0xffffffffu, s3, 2);
            fin0 = (hi ? p[4] : p[0]) + r0;
            fin1 = (hi ? p[5] : p[1]) + r1;
            fin2 = (hi ? p[6] : p[2]) + r2;
            fin3 = (hi ? p[7] : p[3]) + r3;
        }
        if (val[i]) {
            int quad = (sl & 1) * 2 + (sl >> 1);
            float* op = out + (size_t)row[i] * F + quad * 4;
            asm volatile("red.global.add.v4.f32 [%0], {%1, %2, %3, %4};"
                         :: "l"(op), "f"(fin0), "f"(fin1), "f"(fin2), "f"(fin3)
                         : "memory");
        }
    }
}

// ---------------------------------------------------------------------------
extern "C" void kernel_launch(void* const* d_in, const int* in_sizes, int n_in,
                              void* d_out, int out_size)
{
    const float* x    = (const float*)d_in[0];
    const int*   ei   = (const int*)d_in[1];
    const float* attr = (const float*)d_in[2];
    const float* w    = (const float*)d_in[3];
    float*       out  = (float*)d_out;

    int n_nodes = in_sizes[0] / F;       // 100000
    int n_edges = in_sizes[1] / 2;       // 1600000

    cudaMemsetAsync(d_out, 0, (size_t)out_size * sizeof(float));

    build_table_kernel<<<592, 256>>>(x, w, n_nodes);

    int ek_blocks = (n_edges + EPB - 1) / EPB;
    edge_kernel<<<ek_blocks, 256>>>(ei, attr, out, n_edges);
}